// round 1
// baseline (speedup 1.0000x reference)
#include <cuda_runtime.h>
#include <cuda_bf16.h>

// DifferentiableKendallTau: tau = sum_{i<j} tanh((p_j-p_i)*(t_j-t_i)/0.1) / (n*(n-1)/2)
// n = 8192. Tiled all-pairs, MUFU.TANH, double-precision final accumulation.

#define TILE 256

__device__ double g_tau_sum;

__global__ void ktau_zero_kernel() {
    g_tau_sum = 0.0;
}

__device__ __forceinline__ float fast_tanh(float x) {
    float y;
    asm("tanh.approx.f32 %0, %1;" : "=f"(y) : "f"(x));
    return y;
}

__global__ void __launch_bounds__(TILE, 8)
ktau_main_kernel(const float* __restrict__ pred,
                 const float* __restrict__ target,
                 int nt /* number of tiles */) {
    // Decode linear block id -> (bi, bj) with bi <= bj (upper-triangular tile pairs).
    int b = blockIdx.x;
    int bi = 0;
    int rem = b;
    while (rem >= nt - bi) { rem -= nt - bi; bi++; }
    int bj = bi + rem;

    __shared__ float sp[TILE];
    __shared__ float st[TILE];
    __shared__ float warp_sums[TILE / 32];

    int tid = threadIdx.x;

    // Stage the i-tile. Fold temperature (1/0.1 = 10) into the p side only:
    // (10*p_j - 10*p_i) * (t_j - t_i) == 10 * pd * td.
    sp[tid] = 10.0f * pred[bi * TILE + tid];
    st[tid] = target[bi * TILE + tid];
    __syncthreads();

    // This thread owns one j column.
    int j = bj * TILE + tid;
    float pj = 10.0f * pred[j];
    float tj = target[j];

    float acc = 0.0f;

    if (bi != bj) {
        // All i in this tile are strictly less than all j: unconditional loop.
        #pragma unroll 8
        for (int i = 0; i < TILE; i++) {
            float x = (pj - sp[i]) * (tj - st[i]);
            acc += fast_tanh(x);
        }
    } else {
        // Diagonal tile: only i < j, i.e. local i < tid.
        #pragma unroll 4
        for (int i = 0; i < tid; i++) {
            float x = (pj - sp[i]) * (tj - st[i]);
            acc += fast_tanh(x);
        }
    }

    // Warp reduction.
    #pragma unroll
    for (int off = 16; off > 0; off >>= 1)
        acc += __shfl_xor_sync(0xFFFFFFFFu, acc, off);

    int lane = tid & 31;
    int wid  = tid >> 5;
    if (lane == 0) warp_sums[wid] = acc;
    __syncthreads();

    if (tid == 0) {
        double s = 0.0;
        #pragma unroll
        for (int w = 0; w < TILE / 32; w++) s += (double)warp_sums[w];
        atomicAdd(&g_tau_sum, s);
    }
}

__global__ void ktau_finalize_kernel(float* __restrict__ out, double inv_pairs) {
    out[0] = (float)(g_tau_sum * inv_pairs);
}

extern "C" void kernel_launch(void* const* d_in, const int* in_sizes, int n_in,
                              void* d_out, int out_size) {
    const float* pred   = (const float*)d_in[0];
    const float* target = (const float*)d_in[1];
    float* out = (float*)d_out;

    int n = in_sizes[0];          // 8192
    int nt = n / TILE;            // 32
    int nblocks = nt * (nt + 1) / 2;  // 528

    double n_pairs = 0.5 * (double)n * (double)(n - 1);
    double inv_pairs = 1.0 / n_pairs;

    ktau_zero_kernel<<<1, 1>>>();
    ktau_main_kernel<<<nblocks, TILE>>>(pred, target, nt);
    ktau_finalize_kernel<<<1, 1>>>(out, inv_pairs);
}